// round 4
// baseline (speedup 1.0000x reference)
#include <cuda_runtime.h>
#include <cstdint>
#include <cstddef>

#define D_DIM 64
#define L_DIM 100
#define B_DIM 256
#define H_DIM 10000
#define HC    64                 // h-columns per block
#define PITCH 68                 // floats per tile row (64 data + 4 pad)
#define TILE_FLOATS (L_DIM * PITCH)
#define NBUF  3
#define NTHR  256
#define BB    128                // batches per block

// per-(d,b): {lo*PITCH (bits), hi*PITCH (bits), alpha, 0}
__device__ float4 g_scratch[D_DIM * B_DIM];

__global__ void __launch_bounds__(256) precomp_kernel(const float* __restrict__ x) {
    int idx = blockIdx.x * 256 + threadIdx.x;
    if (idx >= D_DIM * B_DIM) return;
    int d = idx >> 8;
    int b = idx & 255;
    float xv = x[b * D_DIM + d];
    float xn = fminf(fmaxf(xv * (float)(L_DIM - 1), 0.0f), (float)(L_DIM - 1));
    float fl = floorf(xn);
    int lo = (int)fl;
    int hi = min(lo + 1, L_DIM - 1);
    float a = xn - fl;
    float4 r;
    r.x = __int_as_float(lo * PITCH);
    r.y = __int_as_float(hi * PITCH);
    r.z = a;
    r.w = 0.0f;
    g_scratch[idx] = r;
}

__device__ __forceinline__ void cp_async16(uint32_t smem, const void* gmem) {
    asm volatile("cp.async.cg.shared.global [%0], [%1], 16;\n" :: "r"(smem), "l"(gmem));
}
__device__ __forceinline__ void cp_commit() {
    asm volatile("cp.async.commit_group;\n" ::: "memory");
}
template <int N>
__device__ __forceinline__ void cp_wait() {
    asm volatile("cp.async.wait_group %0;\n" :: "n"(N) : "memory");
}

// Blackwell packed fp32x2 helpers
__device__ __forceinline__ unsigned long long pk2(float lo, float hi) {
    unsigned long long r;
    asm("mov.b64 %0, {%1, %2};" : "=l"(r) : "f"(lo), "f"(hi));
    return r;
}
__device__ __forceinline__ unsigned long long ffma2(unsigned long long a,
                                                    unsigned long long b,
                                                    unsigned long long c) {
    unsigned long long d;
    asm("fma.rn.f32x2 %0, %1, %2, %3;" : "=l"(d) : "l"(a), "l"(b), "l"(c));
    return d;
}

__global__ void __launch_bounds__(NTHR, 2) encode_kernel(const float* __restrict__ base,
                                                         float* __restrict__ out) {
    __shared__ float  tile[NBUF][TILE_FLOATS];
    __shared__ float4 sscr[NBUF][BB];

    const int tid   = threadIdx.x;
    const int hg    = tid & 15;        // which float4 within the 64-column slice
    const int bg    = tid >> 4;        // batch group within block: 0..15 (8 batches each)
    const int slice = blockIdx.x >> 1;
    const int bbase = (blockIdx.x & 1) * BB;
    const int h0    = slice * HC;
    const int h     = h0 + hg * 4;
    const bool h_ok = (h < H_DIM);

    // stage base[d, 0..99, h0..h0+63] AND scratch[d, bbase..bbase+127] into buffer buf
    auto load_stage = [&](int d, int buf) {
        const float* src = base + (size_t)d * (L_DIM * H_DIM) + h0;
        uint32_t sbase = (uint32_t)__cvta_generic_to_shared(&tile[buf][0]);
        for (int v = tid; v < L_DIM * 16; v += NTHR) {
            int row = v >> 4;
            int col = v & 15;
            int hh = h0 + col * 4;
            if (hh < H_DIM) {
                cp_async16(sbase + (uint32_t)(row * PITCH + col * 4) * 4,
                           src + (size_t)row * H_DIM + col * 4);
            }
        }
        if (tid < BB) {
            uint32_t sdst = (uint32_t)__cvta_generic_to_shared(&sscr[buf][tid]);
            cp_async16(sdst, &g_scratch[d * B_DIM + bbase + tid]);
        }
        cp_commit();
    };

    unsigned long long acc[8][2];
#pragma unroll
    for (int i = 0; i < 8; ++i) { acc[i][0] = 0ull; acc[i][1] = 0ull; }

    load_stage(0, 0);
    load_stage(1, 1);

    for (int d = 0; d < D_DIM; ++d) {
        if (d == D_DIM - 1) { cp_wait<0>(); } else { cp_wait<1>(); }
        __syncthreads();                          // tile(d)+scr(d) visible; d-1 consumers done
        if (d + 2 < D_DIM) load_stage(d + 2, (d + 2) % NBUF);

        const float*  tb = tile[d % NBUF];
        const float4* sc = &sscr[d % NBUF][bg * 8];
#pragma unroll
        for (int i = 0; i < 8; ++i) {
            float4 s = sc[i];                     // LDS.128 broadcast within 16-lane group
            int off_lo = __float_as_int(s.x);
            int off_hi = __float_as_int(s.y);
            float a  = s.z;
            unsigned long long wa = pk2(a, a);
            unsigned long long w0 = pk2(1.0f - a, 1.0f - a);
            ulonglong2 vl = *reinterpret_cast<const ulonglong2*>(tb + off_lo + hg * 4);
            ulonglong2 vh = *reinterpret_cast<const ulonglong2*>(tb + off_hi + hg * 4);
            acc[i][0] = ffma2(w0, vl.x, acc[i][0]);
            acc[i][1] = ffma2(w0, vl.y, acc[i][1]);
            acc[i][0] = ffma2(wa, vh.x, acc[i][0]);
            acc[i][1] = ffma2(wa, vh.y, acc[i][1]);
        }
    }

    if (h_ok) {
#pragma unroll
        for (int i = 0; i < 8; ++i) {
            ulonglong2 o;
            o.x = acc[i][0];
            o.y = acc[i][1];
            *reinterpret_cast<ulonglong2*>(out + (size_t)(bbase + bg * 8 + i) * H_DIM + h) = o;
        }
    }
}

__global__ void __launch_bounds__(256) normalize_kernel(float* __restrict__ out) {
    int b = blockIdx.x;
    float* row = out + (size_t)b * H_DIM;

    float ss = 0.0f;
    for (int i = threadIdx.x * 4; i < H_DIM; i += 256 * 4) {
        float4 v = *reinterpret_cast<const float4*>(row + i);
        ss += v.x * v.x + v.y * v.y + v.z * v.z + v.w * v.w;
    }
#pragma unroll
    for (int o = 16; o; o >>= 1) ss += __shfl_down_sync(0xffffffffu, ss, o);

    __shared__ float red[8];
    __shared__ float inv_s;
    if ((threadIdx.x & 31) == 0) red[threadIdx.x >> 5] = ss;
    __syncthreads();
    if (threadIdx.x == 0) {
        float t = 0.0f;
#pragma unroll
        for (int i = 0; i < 8; ++i) t += red[i];
        inv_s = rsqrtf(t);
    }
    __syncthreads();
    float inv = inv_s;

    for (int i = threadIdx.x * 4; i < H_DIM; i += 256 * 4) {
        float4 v = *reinterpret_cast<const float4*>(row + i);
        v.x *= inv; v.y *= inv; v.z *= inv; v.w *= inv;
        *reinterpret_cast<float4*>(row + i) = v;
    }
}

extern "C" void kernel_launch(void* const* d_in, const int* in_sizes, int n_in,
                              void* d_out, int out_size) {
    const float* x;
    const float* base;
    if (in_sizes[0] == B_DIM * D_DIM) {
        x = (const float*)d_in[0];
        base = (const float*)d_in[1];
    } else {
        x = (const float*)d_in[1];
        base = (const float*)d_in[0];
    }
    float* out = (float*)d_out;

    precomp_kernel<<<(D_DIM * B_DIM + 255) / 256, 256>>>(x);

    int nslices = (H_DIM + HC - 1) / HC;   // 157
    encode_kernel<<<nslices * 2, NTHR>>>(base, out);

    normalize_kernel<<<B_DIM, 256>>>(out);
}

// round 5
// speedup vs baseline: 1.1004x; 1.1004x over previous
#include <cuda_runtime.h>
#include <cstdint>
#include <cstddef>

#define D_DIM 64
#define L_DIM 100
#define B_DIM 256
#define H_DIM 10000
#define HC    32                 // h-columns per block
#define PITCH 36                 // floats per tile row (32 data + 4 pad)
#define DPS   2                  // d's per pipeline stage
#define NSTG  (D_DIM / DPS)      // 32 stages
#define TILE_FLOATS (L_DIM * PITCH)
#define NBUF  3
#define NTHR  512

// per-(d,b): {lo*PITCH (bits), hi*PITCH (bits), alpha, 0}
__device__ float4 g_scratch[D_DIM * B_DIM];
__device__ int    g_dummy;

__global__ void dummy_kernel() {
    if (threadIdx.x == 0 && blockIdx.x == 0) g_dummy = 1;
}

__global__ void __launch_bounds__(256) precomp_kernel(const float* __restrict__ x) {
    int idx = blockIdx.x * 256 + threadIdx.x;
    if (idx >= D_DIM * B_DIM) return;
    int d = idx >> 8;
    int b = idx & 255;
    float xv = x[b * D_DIM + d];
    float xn = fminf(fmaxf(xv * (float)(L_DIM - 1), 0.0f), (float)(L_DIM - 1));
    float fl = floorf(xn);
    int lo = (int)fl;
    int hi = min(lo + 1, L_DIM - 1);
    float a = xn - fl;
    float4 r;
    r.x = __int_as_float(lo * PITCH);
    r.y = __int_as_float(hi * PITCH);
    r.z = a;
    r.w = 0.0f;
    g_scratch[idx] = r;
}

__device__ __forceinline__ void cp_async16(uint32_t smem, const void* gmem) {
    asm volatile("cp.async.cg.shared.global [%0], [%1], 16;\n" :: "r"(smem), "l"(gmem));
}
__device__ __forceinline__ void cp_commit() {
    asm volatile("cp.async.commit_group;\n" ::: "memory");
}
template <int N>
__device__ __forceinline__ void cp_wait() {
    asm volatile("cp.async.wait_group %0;\n" :: "n"(N) : "memory");
}

// Blackwell packed fp32x2 helpers
__device__ __forceinline__ unsigned long long pk2(float v) {
    unsigned long long r;
    asm("mov.b64 %0, {%1, %2};" : "=l"(r) : "f"(v), "f"(v));
    return r;
}
__device__ __forceinline__ unsigned long long ffma2(unsigned long long a,
                                                    unsigned long long b,
                                                    unsigned long long c) {
    unsigned long long d;
    asm("fma.rn.f32x2 %0, %1, %2, %3;" : "=l"(d) : "l"(a), "l"(b), "l"(c));
    return d;
}

__global__ void __launch_bounds__(NTHR, 2) encode_kernel(const float* __restrict__ base,
                                                         float* __restrict__ out) {
    __shared__ float  tile[NBUF][DPS * TILE_FLOATS];
    __shared__ float4 sscr[NBUF][DPS * B_DIM];

    const int tid = threadIdx.x;
    const int hg  = tid & 7;        // which float4 within the 32-column slice
    const int bg  = tid >> 3;       // batch group: 4 batches per thread (0..63)
    const int h0  = blockIdx.x * HC;
    const int h   = h0 + hg * 4;
    const bool h_ok = (h < H_DIM);

    // stage s covers d = 2s, 2s+1: base[d, 0..99, h0..h0+31] and scratch rows
    auto load_stage = [&](int s, int buf) {
        uint32_t sbase = (uint32_t)__cvta_generic_to_shared(&tile[buf][0]);
        for (int v = tid; v < L_DIM * 8 * DPS; v += NTHR) {
            int dd  = v / (L_DIM * 8);
            int rem = v - dd * (L_DIM * 8);
            int row = rem >> 3;
            int col = rem & 7;
            int hh = h0 + col * 4;
            if (hh < H_DIM) {
                const float* src = base + (size_t)(s * DPS + dd) * (L_DIM * H_DIM) + h0;
                cp_async16(sbase + (uint32_t)(dd * TILE_FLOATS + row * PITCH + col * 4) * 4,
                           src + (size_t)row * H_DIM + col * 4);
            }
        }
        // scratch: 2 d's * 256 batches = 512 float4s, one per thread
        {
            uint32_t sdst = (uint32_t)__cvta_generic_to_shared(&sscr[buf][tid]);
            cp_async16(sdst, &g_scratch[s * (DPS * B_DIM) + tid]);
        }
        cp_commit();
    };

    unsigned long long acc[4][2];
#pragma unroll
    for (int i = 0; i < 4; ++i) { acc[i][0] = 0ull; acc[i][1] = 0ull; }

    load_stage(0, 0);
    load_stage(1, 1);

    for (int s = 0; s < NSTG; ++s) {
        if (s == NSTG - 1) { cp_wait<0>(); } else { cp_wait<1>(); }
        __syncthreads();                          // stage(s) visible; stage(s-1) consumers done
        if (s + 2 < NSTG) load_stage(s + 2, (s + 2) % NBUF);

        const float* tb0 = &tile[s % NBUF][0];
#pragma unroll
        for (int dd = 0; dd < DPS; ++dd) {
            const float*  tb = tb0 + dd * TILE_FLOATS;
            const float4* sc = &sscr[s % NBUF][dd * B_DIM + bg * 4];
#pragma unroll
            for (int i = 0; i < 4; ++i) {
                float4 ssc = sc[i];               // LDS.128 broadcast within 8-lane group
                int off_lo = __float_as_int(ssc.x);
                int off_hi = __float_as_int(ssc.y);
                float a  = ssc.z;
                unsigned long long wa = pk2(a);
                unsigned long long w0 = pk2(1.0f - a);
                ulonglong2 vl = *reinterpret_cast<const ulonglong2*>(tb + off_lo + hg * 4);
                ulonglong2 vh = *reinterpret_cast<const ulonglong2*>(tb + off_hi + hg * 4);
                acc[i][0] = ffma2(w0, vl.x, acc[i][0]);
                acc[i][1] = ffma2(w0, vl.y, acc[i][1]);
                acc[i][0] = ffma2(wa, vh.x, acc[i][0]);
                acc[i][1] = ffma2(wa, vh.y, acc[i][1]);
            }
        }
    }

    if (h_ok) {
#pragma unroll
        for (int i = 0; i < 4; ++i) {
            ulonglong2 o;
            o.x = acc[i][0];
            o.y = acc[i][1];
            *reinterpret_cast<ulonglong2*>(out + (size_t)(bg * 4 + i) * H_DIM + h) = o;
        }
    }
}

__global__ void __launch_bounds__(256) normalize_kernel(float* __restrict__ out) {
    int b = blockIdx.x;
    float* row = out + (size_t)b * H_DIM;

    float ss = 0.0f;
    for (int i = threadIdx.x * 4; i < H_DIM; i += 256 * 4) {
        float4 v = *reinterpret_cast<const float4*>(row + i);
        ss += v.x * v.x + v.y * v.y + v.z * v.z + v.w * v.w;
    }
#pragma unroll
    for (int o = 16; o; o >>= 1) ss += __shfl_down_sync(0xffffffffu, ss, o);

    __shared__ float red[8];
    __shared__ float inv_s;
    if ((threadIdx.x & 31) == 0) red[threadIdx.x >> 5] = ss;
    __syncthreads();
    if (threadIdx.x == 0) {
        float t = 0.0f;
#pragma unroll
        for (int i = 0; i < 8; ++i) t += red[i];
        inv_s = rsqrtf(t);
    }
    __syncthreads();
    float inv = inv_s;

    for (int i = threadIdx.x * 4; i < H_DIM; i += 256 * 4) {
        float4 v = *reinterpret_cast<const float4*>(row + i);
        v.x *= inv; v.y *= inv; v.z *= inv; v.w *= inv;
        *reinterpret_cast<float4*>(row + i) = v;
    }
}

extern "C" void kernel_launch(void* const* d_in, const int* in_sizes, int n_in,
                              void* d_out, int out_size) {
    const float* x;
    const float* base;
    if (in_sizes[0] == B_DIM * D_DIM) {
        x = (const float*)d_in[0];
        base = (const float*)d_in[1];
    } else {
        x = (const float*)d_in[1];
        base = (const float*)d_in[0];
    }
    float* out = (float*)d_out;

    // two dummy launches: shift the ncu -s 5 -c 1 window so slot 6 == encode
    dummy_kernel<<<1, 32>>>();
    dummy_kernel<<<1, 32>>>();

    precomp_kernel<<<(D_DIM * B_DIM + 255) / 256, 256>>>(x);

    int nblocks = (H_DIM + HC - 1) / HC;   // 313
    encode_kernel<<<nblocks, NTHR>>>(base, out);

    normalize_kernel<<<B_DIM, 256>>>(out);
}

// round 6
// speedup vs baseline: 1.2854x; 1.1682x over previous
#include <cuda_runtime.h>
#include <cuda.h>
#include <cstdint>
#include <cstddef>
#include <cstring>

#define D_DIM 64
#define L_DIM 100
#define B_DIM 256
#define H_DIM 10000
#define HC    32                 // h-columns per block
#define PITCH 32                 // floats per tile row (dense, TMA-packed)
#define TILE_FLOATS (L_DIM * PITCH)
#define TILE_BYTES  (TILE_FLOATS * 4)       // 12800
#define SCR_BYTES   (B_DIM * 16)            // 4096
#define NBUF  6
#define NTHR  512

// per-(d,b): {lo*PITCH (bits), hi*PITCH (bits), alpha, 0}
__device__ float4 g_scratch[D_DIM * B_DIM];
__device__ int    g_dummy;

__global__ void dummy_kernel() {
    if (threadIdx.x == 0 && blockIdx.x == 0) g_dummy = 1;
}

__global__ void __launch_bounds__(256) precomp_kernel(const float* __restrict__ x) {
    int idx = blockIdx.x * 256 + threadIdx.x;
    if (idx >= D_DIM * B_DIM) return;
    int d = idx >> 8;
    int b = idx & 255;
    float xv = x[b * D_DIM + d];
    float xn = fminf(fmaxf(xv * (float)(L_DIM - 1), 0.0f), (float)(L_DIM - 1));
    float fl = floorf(xn);
    int lo = (int)fl;
    int hi = min(lo + 1, L_DIM - 1);
    float a = xn - fl;
    float4 r;
    r.x = __int_as_float(lo * PITCH);
    r.y = __int_as_float(hi * PITCH);
    r.z = a;
    r.w = 0.0f;
    g_scratch[idx] = r;
}

// ---- Blackwell packed fp32x2 helpers ----
__device__ __forceinline__ unsigned long long pk2(float v) {
    unsigned long long r;
    asm("mov.b64 %0, {%1, %2};" : "=l"(r) : "f"(v), "f"(v));
    return r;
}
__device__ __forceinline__ unsigned long long ffma2(unsigned long long a,
                                                    unsigned long long b,
                                                    unsigned long long c) {
    unsigned long long d;
    asm("fma.rn.f32x2 %0, %1, %2, %3;" : "=l"(d) : "l"(a), "l"(b), "l"(c));
    return d;
}

// ---- mbarrier / TMA helpers ----
__device__ __forceinline__ void mbar_init(uint32_t addr, uint32_t count) {
    asm volatile("mbarrier.init.shared.b64 [%0], %1;" :: "r"(addr), "r"(count) : "memory");
}
__device__ __forceinline__ void mbar_expect_tx(uint32_t addr, uint32_t bytes) {
    asm volatile("mbarrier.arrive.expect_tx.shared.b64 _, [%0], %1;"
                 :: "r"(addr), "r"(bytes) : "memory");
}
__device__ __forceinline__ void mbar_wait(uint32_t addr, uint32_t parity) {
    asm volatile(
        "{\n\t.reg .pred P;\n"
        "WL_%=:\n\t"
        "mbarrier.try_wait.parity.shared::cta.b64 P, [%0], %1, 0x989680;\n\t"
        "@!P bra WL_%=;\n\t}"
        :: "r"(addr), "r"(parity) : "memory");
}
__device__ __forceinline__ void tma_load_2d(uint32_t smem_dst, const CUtensorMap* tmap,
                                            int cx, int cy, uint32_t mbar) {
    asm volatile(
        "cp.async.bulk.tensor.2d.shared::cta.global.tile.mbarrier::complete_tx::bytes "
        "[%0], [%1, {%2, %3}], [%4];"
        :: "r"(smem_dst), "l"(tmap), "r"(cx), "r"(cy), "r"(mbar) : "memory");
}
__device__ __forceinline__ void bulk_copy_g2s(uint32_t smem_dst, const void* gsrc,
                                              uint32_t bytes, uint32_t mbar) {
    unsigned long long ga = (unsigned long long)__cvta_generic_to_global(gsrc);
    asm volatile(
        "cp.async.bulk.shared::cta.global.mbarrier::complete_tx::bytes [%0], [%1], %2, [%3];"
        :: "r"(smem_dst), "l"(ga), "r"(bytes), "r"(mbar) : "memory");
}

__global__ void __launch_bounds__(NTHR, 2) encode_kernel(
        const __grid_constant__ CUtensorMap tmap,
        float* __restrict__ out) {
    __shared__ float  tile[NBUF][TILE_FLOATS];
    __shared__ float4 sscr[NBUF][B_DIM];
    __shared__ __align__(8) unsigned long long mbar[NBUF];

    const int tid = threadIdx.x;
    const int hg  = tid & 7;        // which float4 within the 32-column slice
    const int bg  = tid >> 3;       // batch group: 4 batches per thread (0..63)
    const int h0  = blockIdx.x * HC;
    const int h   = h0 + hg * 4;
    const bool h_ok = (h < H_DIM);

    if (tid == 0) {
#pragma unroll
        for (int i = 0; i < NBUF; ++i)
            mbar_init((uint32_t)__cvta_generic_to_shared(&mbar[i]), 1);
        asm volatile("fence.proxy.async.shared::cta;" ::: "memory");
    }
    __syncthreads();

    auto issue = [&](int d) {
        if (tid == 0) {
            int slot = d % NBUF;
            uint32_t bar = (uint32_t)__cvta_generic_to_shared(&mbar[slot]);
            mbar_expect_tx(bar, TILE_BYTES + SCR_BYTES);
            tma_load_2d((uint32_t)__cvta_generic_to_shared(&tile[slot][0]),
                        &tmap, h0, d * L_DIM, bar);
            bulk_copy_g2s((uint32_t)__cvta_generic_to_shared(&sscr[slot][0]),
                          &g_scratch[d * B_DIM], SCR_BYTES, bar);
        }
    };

    // prologue: fill NBUF-1 slots
#pragma unroll
    for (int d = 0; d < NBUF - 1; ++d) issue(d);

    unsigned long long acc[4][2];
#pragma unroll
    for (int i = 0; i < 4; ++i) { acc[i][0] = 0ull; acc[i][1] = 0ull; }

    for (int d = 0; d < D_DIM; ++d) {
        const int slot = d % NBUF;
        uint32_t bar = (uint32_t)__cvta_generic_to_shared(&mbar[slot]);
        mbar_wait(bar, (d / NBUF) & 1);
        __syncthreads();                    // all consumers of stage d-1 are done past here
        if (d + NBUF - 1 < D_DIM) issue(d + NBUF - 1);

        const float*  tb = tile[slot];
        const float4* sc = &sscr[slot][bg * 4];
#pragma unroll
        for (int i = 0; i < 4; ++i) {
            float4 s = sc[i];               // LDS.128 broadcast within 8-lane group
            int off_lo = __float_as_int(s.x);
            int off_hi = __float_as_int(s.y);
            float a  = s.z;
            unsigned long long wa = pk2(a);
            unsigned long long w0 = pk2(1.0f - a);
            ulonglong2 vl = *reinterpret_cast<const ulonglong2*>(tb + off_lo + hg * 4);
            ulonglong2 vh = *reinterpret_cast<const ulonglong2*>(tb + off_hi + hg * 4);
            acc[i][0] = ffma2(w0, vl.x, acc[i][0]);
            acc[i][1] = ffma2(w0, vl.y, acc[i][1]);
            acc[i][0] = ffma2(wa, vh.x, acc[i][0]);
            acc[i][1] = ffma2(wa, vh.y, acc[i][1]);
        }
    }

    if (h_ok) {
#pragma unroll
        for (int i = 0; i < 4; ++i) {
            ulonglong2 o;
            o.x = acc[i][0];
            o.y = acc[i][1];
            *reinterpret_cast<ulonglong2*>(out + (size_t)(bg * 4 + i) * H_DIM + h) = o;
        }
    }
}

__global__ void __launch_bounds__(256) normalize_kernel(float* __restrict__ out) {
    int b = blockIdx.x;
    float* row = out + (size_t)b * H_DIM;

    float ss = 0.0f;
    for (int i = threadIdx.x * 4; i < H_DIM; i += 256 * 4) {
        float4 v = *reinterpret_cast<const float4*>(row + i);
        ss += v.x * v.x + v.y * v.y + v.z * v.z + v.w * v.w;
    }
#pragma unroll
    for (int o = 16; o; o >>= 1) ss += __shfl_down_sync(0xffffffffu, ss, o);

    __shared__ float red[8];
    __shared__ float inv_s;
    if ((threadIdx.x & 31) == 0) red[threadIdx.x >> 5] = ss;
    __syncthreads();
    if (threadIdx.x == 0) {
        float t = 0.0f;
#pragma unroll
        for (int i = 0; i < 8; ++i) t += red[i];
        inv_s = rsqrtf(t);
    }
    __syncthreads();
    float inv = inv_s;

    for (int i = threadIdx.x * 4; i < H_DIM; i += 256 * 4) {
        float4 v = *reinterpret_cast<const float4*>(row + i);
        v.x *= inv; v.y *= inv; v.z *= inv; v.w *= inv;
        *reinterpret_cast<float4*>(row + i) = v;
    }
}

// ---- host-side tensor-map construction (no -lcuda needed) ----
typedef CUresult (*encode_tiled_fn)(
    CUtensorMap*, CUtensorMapDataType, cuuint32_t, void*,
    const cuuint64_t*, const cuuint64_t*, const cuuint32_t*, const cuuint32_t*,
    CUtensorMapInterleave, CUtensorMapSwizzle, CUtensorMapL2promotion,
    CUtensorMapFloatOOBfill);

static encode_tiled_fn get_encode_fn() {
    static encode_tiled_fn fn = nullptr;
    if (!fn) {
        void* p = nullptr;
        cudaDriverEntryPointQueryResult qr;
        cudaGetDriverEntryPointByVersion("cuTensorMapEncodeTiled", &p, 12000,
                                         cudaEnableDefault, &qr);
        fn = (encode_tiled_fn)p;
    }
    return fn;
}

extern "C" void kernel_launch(void* const* d_in, const int* in_sizes, int n_in,
                              void* d_out, int out_size) {
    const float* x;
    const float* base;
    if (in_sizes[0] == B_DIM * D_DIM) {
        x = (const float*)d_in[0];
        base = (const float*)d_in[1];
    } else {
        x = (const float*)d_in[1];
        base = (const float*)d_in[0];
    }
    float* out = (float*)d_out;

    // base viewed as 2D: [D*L rows of H floats]; box = [HC, L]
    CUtensorMap tmap;
    memset(&tmap, 0, sizeof(tmap));
    {
        encode_tiled_fn enc = get_encode_fn();
        cuuint64_t dims[2]    = {(cuuint64_t)H_DIM, (cuuint64_t)(D_DIM * L_DIM)};
        cuuint64_t strides[1] = {(cuuint64_t)H_DIM * 4};
        cuuint32_t box[2]     = {HC, L_DIM};
        cuuint32_t estr[2]    = {1, 1};
        enc(&tmap, CU_TENSOR_MAP_DATA_TYPE_FLOAT32, 2, (void*)base,
            dims, strides, box, estr,
            CU_TENSOR_MAP_INTERLEAVE_NONE, CU_TENSOR_MAP_SWIZZLE_NONE,
            CU_TENSOR_MAP_L2_PROMOTION_L2_128B, CU_TENSOR_MAP_FLOAT_OOB_FILL_NONE);
    }

    // two dummy launches keep the ncu -s 5 -c 1 window on encode
    dummy_kernel<<<1, 32>>>();
    dummy_kernel<<<1, 32>>>();

    precomp_kernel<<<(D_DIM * B_DIM + 255) / 256, 256>>>(x);

    int nblocks = (H_DIM + HC - 1) / HC;   // 313
    encode_kernel<<<nblocks, NTHR>>>(tmap, out);

    normalize_kernel<<<B_DIM, 256>>>(out);
}

// round 7
// speedup vs baseline: 1.4213x; 1.1057x over previous
#include <cuda_runtime.h>
#include <cuda.h>
#include <cstdint>
#include <cstddef>
#include <cstring>

#define D_DIM 64
#define L_DIM 100
#define B_DIM 256
#define H_DIM 10000
#define HC    32                 // h-columns per block
#define PITCH 32                 // floats per tile row (dense, TMA-packed)
#define TILE_FLOATS (L_DIM * PITCH)
#define TILE_BYTES  (TILE_FLOATS * 4)       // 12800
#define SCR_BYTES   (B_DIM * 16)            // 4096
#define NBUF  6
#define NTHR  512
#define NWARP (NTHR / 32)

// per-(d,b): {lo*PITCH (bits), hi*PITCH (bits), alpha, 0}
__device__ float4 g_scratch[D_DIM * B_DIM];
__device__ int    g_dummy;

__global__ void dummy_kernel() {
    if (threadIdx.x == 0 && blockIdx.x == 0) g_dummy = 1;
}

__global__ void __launch_bounds__(256) precomp_kernel(const float* __restrict__ x) {
    int idx = blockIdx.x * 256 + threadIdx.x;
    if (idx >= D_DIM * B_DIM) return;
    int d = idx >> 8;
    int b = idx & 255;
    float xv = x[b * D_DIM + d];
    float xn = fminf(fmaxf(xv * (float)(L_DIM - 1), 0.0f), (float)(L_DIM - 1));
    float fl = floorf(xn);
    int lo = (int)fl;
    int hi = min(lo + 1, L_DIM - 1);
    float a = xn - fl;
    float4 r;
    r.x = __int_as_float(lo * PITCH);
    r.y = __int_as_float(hi * PITCH);
    r.z = a;
    r.w = 0.0f;
    g_scratch[idx] = r;
}

// ---- Blackwell packed fp32x2 helpers ----
__device__ __forceinline__ unsigned long long pk2(float v) {
    unsigned long long r;
    asm("mov.b64 %0, {%1, %2};" : "=l"(r) : "f"(v), "f"(v));
    return r;
}
__device__ __forceinline__ unsigned long long ffma2(unsigned long long a,
                                                    unsigned long long b,
                                                    unsigned long long c) {
    unsigned long long d;
    asm("fma.rn.f32x2 %0, %1, %2, %3;" : "=l"(d) : "l"(a), "l"(b), "l"(c));
    return d;
}

// ---- mbarrier / TMA helpers ----
__device__ __forceinline__ void mbar_init(uint32_t addr, uint32_t count) {
    asm volatile("mbarrier.init.shared.b64 [%0], %1;" :: "r"(addr), "r"(count) : "memory");
}
__device__ __forceinline__ void mbar_expect_tx(uint32_t addr, uint32_t bytes) {
    asm volatile("mbarrier.arrive.expect_tx.shared.b64 _, [%0], %1;"
                 :: "r"(addr), "r"(bytes) : "memory");
}
__device__ __forceinline__ void mbar_arrive(uint32_t addr) {
    asm volatile("mbarrier.arrive.release.cta.shared::cta.b64 _, [%0];"
                 :: "r"(addr) : "memory");
}
__device__ __forceinline__ void mbar_wait_acq(uint32_t addr, uint32_t parity) {
    asm volatile(
        "{\n\t.reg .pred P;\n"
        "WL_%=:\n\t"
        "mbarrier.try_wait.parity.acquire.cta.shared::cta.b64 P, [%0], %1, 0x989680;\n\t"
        "@!P bra WL_%=;\n\t}"
        :: "r"(addr), "r"(parity) : "memory");
}
__device__ __forceinline__ void tma_load_2d(uint32_t smem_dst, const CUtensorMap* tmap,
                                            int cx, int cy, uint32_t mbar) {
    asm volatile(
        "cp.async.bulk.tensor.2d.shared::cta.global.tile.mbarrier::complete_tx::bytes "
        "[%0], [%1, {%2, %3}], [%4];"
        :: "r"(smem_dst), "l"(tmap), "r"(cx), "r"(cy), "r"(mbar) : "memory");
}
__device__ __forceinline__ void bulk_copy_g2s(uint32_t smem_dst, const void* gsrc,
                                              uint32_t bytes, uint32_t mbar) {
    unsigned long long ga = (unsigned long long)__cvta_generic_to_global(gsrc);
    asm volatile(
        "cp.async.bulk.shared::cta.global.mbarrier::complete_tx::bytes [%0], [%1], %2, [%3];"
        :: "r"(smem_dst), "l"(ga), "r"(bytes), "r"(mbar) : "memory");
}

__global__ void __launch_bounds__(NTHR, 2) encode_kernel(
        const __grid_constant__ CUtensorMap tmap,
        float* __restrict__ out) {
    __shared__ float  tile[NBUF][TILE_FLOATS];
    __shared__ float4 sscr[NBUF][B_DIM];
    __shared__ __align__(8) unsigned long long mb_full[NBUF];
    __shared__ __align__(8) unsigned long long mb_empty[NBUF];

    const int tid  = threadIdx.x;
    const int lane = tid & 31;
    const int hg   = tid & 7;        // which float4 within the 32-column slice
    const int bg   = tid >> 3;       // batch group: 4 batches per thread (0..63)
    const int h0   = blockIdx.x * HC;
    const int h    = h0 + hg * 4;
    const bool h_ok = (h < H_DIM);

    if (tid == 0) {
#pragma unroll
        for (int i = 0; i < NBUF; ++i) {
            mbar_init((uint32_t)__cvta_generic_to_shared(&mb_full[i]), 1);
            mbar_init((uint32_t)__cvta_generic_to_shared(&mb_empty[i]), NWARP);
        }
        asm volatile("fence.proxy.async.shared::cta;" ::: "memory");
    }
    __syncthreads();          // the only block-wide barrier

    // producer: issue stage d into slot d%NBUF (caller guarantees slot free)
    auto issue = [&](int d) {
        int slot = d % NBUF;
        uint32_t bar = (uint32_t)__cvta_generic_to_shared(&mb_full[slot]);
        mbar_expect_tx(bar, TILE_BYTES + SCR_BYTES);
        tma_load_2d((uint32_t)__cvta_generic_to_shared(&tile[slot][0]),
                    &tmap, h0, d * L_DIM, bar);
        bulk_copy_g2s((uint32_t)__cvta_generic_to_shared(&sscr[slot][0]),
                      &g_scratch[d * B_DIM], SCR_BYTES, bar);
    };

    if (tid == 0) {
#pragma unroll
        for (int d = 0; d < NBUF - 1; ++d) issue(d);   // prologue fill
    }

    unsigned long long acc[4][2];
#pragma unroll
    for (int i = 0; i < 4; ++i) { acc[i][0] = 0ull; acc[i][1] = 0ull; }

    for (int d = 0; d < D_DIM; ++d) {
        const int slot = d % NBUF;
        mbar_wait_acq((uint32_t)__cvta_generic_to_shared(&mb_full[slot]),
                      (uint32_t)((d / NBUF) & 1));

        const float*  tb = tile[slot];
        const float4* sc = &sscr[slot][bg * 4];
#pragma unroll
        for (int i = 0; i < 4; ++i) {
            float4 s = sc[i];               // LDS.128 broadcast within 8-lane group
            int off_lo = __float_as_int(s.x);
            int off_hi = __float_as_int(s.y);
            float a  = s.z;
            unsigned long long wa = pk2(a);
            unsigned long long w0 = pk2(1.0f - a);
            ulonglong2 vl = *reinterpret_cast<const ulonglong2*>(tb + off_lo + hg * 4);
            ulonglong2 vh = *reinterpret_cast<const ulonglong2*>(tb + off_hi + hg * 4);
            acc[i][0] = ffma2(w0, vl.x, acc[i][0]);
            acc[i][1] = ffma2(w0, vl.y, acc[i][1]);
            acc[i][0] = ffma2(wa, vh.x, acc[i][0]);
            acc[i][1] = ffma2(wa, vh.y, acc[i][1]);
        }

        __syncwarp();
        if (lane == 0)
            mbar_arrive((uint32_t)__cvta_generic_to_shared(&mb_empty[slot]));

        // producer refills: stage d+NBUF-1 goes into slot (d-1+NBUF)%NBUF,
        // which is free once all warps consumed stage d-1
        if (tid == 0) {
            int dn = d + NBUF - 1;
            if (dn < D_DIM) {
                int j = dn / NBUF;          // reuse index of that slot
                if (j >= 1)
                    mbar_wait_acq((uint32_t)__cvta_generic_to_shared(&mb_empty[dn % NBUF]),
                                  (uint32_t)((j - 1) & 1));
                issue(dn);
            }
        }
    }

    if (h_ok) {
#pragma unroll
        for (int i = 0; i < 4; ++i) {
            ulonglong2 o;
            o.x = acc[i][0];
            o.y = acc[i][1];
            *reinterpret_cast<ulonglong2*>(out + (size_t)(bg * 4 + i) * H_DIM + h) = o;
        }
    }
}

__global__ void __launch_bounds__(256) normalize_kernel(float* __restrict__ out) {
    int b = blockIdx.x;
    float* row = out + (size_t)b * H_DIM;

    float ss = 0.0f;
    for (int i = threadIdx.x * 4; i < H_DIM; i += 256 * 4) {
        float4 v = *reinterpret_cast<const float4*>(row + i);
        ss += v.x * v.x + v.y * v.y + v.z * v.z + v.w * v.w;
    }
#pragma unroll
    for (int o = 16; o; o >>= 1) ss += __shfl_down_sync(0xffffffffu, ss, o);

    __shared__ float red[8];
    __shared__ float inv_s;
    if ((threadIdx.x & 31) == 0) red[threadIdx.x >> 5] = ss;
    __syncthreads();
    if (threadIdx.x == 0) {
        float t = 0.0f;
#pragma unroll
        for (int i = 0; i < 8; ++i) t += red[i];
        inv_s = rsqrtf(t);
    }
    __syncthreads();
    float inv = inv_s;

    for (int i = threadIdx.x * 4; i < H_DIM; i += 256 * 4) {
        float4 v = *reinterpret_cast<const float4*>(row + i);
        v.x *= inv; v.y *= inv; v.z *= inv; v.w *= inv;
        *reinterpret_cast<float4*>(row + i) = v;
    }
}

// ---- host-side tensor-map construction (no -lcuda needed) ----
typedef CUresult (*encode_tiled_fn)(
    CUtensorMap*, CUtensorMapDataType, cuuint32_t, void*,
    const cuuint64_t*, const cuuint64_t*, const cuuint32_t*, const cuuint32_t*,
    CUtensorMapInterleave, CUtensorMapSwizzle, CUtensorMapL2promotion,
    CUtensorMapFloatOOBfill);

static encode_tiled_fn get_encode_fn() {
    static encode_tiled_fn fn = nullptr;
    if (!fn) {
        void* p = nullptr;
        cudaDriverEntryPointQueryResult qr;
        cudaGetDriverEntryPointByVersion("cuTensorMapEncodeTiled", &p, 12000,
                                         cudaEnableDefault, &qr);
        fn = (encode_tiled_fn)p;
    }
    return fn;
}

extern "C" void kernel_launch(void* const* d_in, const int* in_sizes, int n_in,
                              void* d_out, int out_size) {
    const float* x;
    const float* base;
    if (in_sizes[0] == B_DIM * D_DIM) {
        x = (const float*)d_in[0];
        base = (const float*)d_in[1];
    } else {
        x = (const float*)d_in[1];
        base = (const float*)d_in[0];
    }
    float* out = (float*)d_out;

    // base viewed as 2D: [D*L rows of H floats]; box = [HC, L]
    CUtensorMap tmap;
    memset(&tmap, 0, sizeof(tmap));
    {
        encode_tiled_fn enc = get_encode_fn();
        cuuint64_t dims[2]    = {(cuuint64_t)H_DIM, (cuuint64_t)(D_DIM * L_DIM)};
        cuuint64_t strides[1] = {(cuuint64_t)H_DIM * 4};
        cuuint32_t box[2]     = {HC, L_DIM};
        cuuint32_t estr[2]    = {1, 1};
        enc(&tmap, CU_TENSOR_MAP_DATA_TYPE_FLOAT32, 2, (void*)base,
            dims, strides, box, estr,
            CU_TENSOR_MAP_INTERLEAVE_NONE, CU_TENSOR_MAP_SWIZZLE_NONE,
            CU_TENSOR_MAP_L2_PROMOTION_L2_128B, CU_TENSOR_MAP_FLOAT_OOB_FILL_NONE);
    }

    // two dummy launches keep the ncu -s 5 -c 1 window on encode
    dummy_kernel<<<1, 32>>>();
    dummy_kernel<<<1, 32>>>();

    precomp_kernel<<<(D_DIM * B_DIM + 255) / 256, 256>>>(x);

    int nblocks = (H_DIM + HC - 1) / HC;   // 313
    encode_kernel<<<nblocks, NTHR>>>(tmap, out);

    normalize_kernel<<<B_DIM, 256>>>(out);
}

// round 8
// speedup vs baseline: 1.4253x; 1.0028x over previous
#include <cuda_runtime.h>
#include <cuda.h>
#include <cstdint>
#include <cstddef>
#include <cstring>

#define D_DIM 64
#define L_DIM 100
#define B_DIM 256
#define H_DIM 10000
#define HC    32                 // h-columns per block
#define PITCH 32                 // floats per tile row (dense, TMA-packed)
#define TILE_FLOATS (L_DIM * PITCH)
#define TILE_BYTES  (TILE_FLOATS * 4)       // 12800
#define SCR_BYTES   (B_DIM * 16)            // 4096
#define NBUF  6
#define NTHR  512
#define NWARP (NTHR / 32)

// per-(d,b): {lo*PITCH (bits), hi*PITCH (bits), alpha, 0}
__device__ float4 g_scratch[D_DIM * B_DIM];
__device__ int    g_dummy;

__global__ void dummy_kernel() {
    if (threadIdx.x == 0 && blockIdx.x == 0) g_dummy = 1;
}

__global__ void __launch_bounds__(256) precomp_kernel(const float* __restrict__ x) {
    int idx = blockIdx.x * 256 + threadIdx.x;
    if (idx >= D_DIM * B_DIM) return;
    int d = idx >> 8;
    int b = idx & 255;
    float xv = x[b * D_DIM + d];
    float xn = fminf(fmaxf(xv * (float)(L_DIM - 1), 0.0f), (float)(L_DIM - 1));
    float fl = floorf(xn);
    int lo = (int)fl;
    int hi = min(lo + 1, L_DIM - 1);
    float a = xn - fl;
    float4 r;
    r.x = __int_as_float(lo * PITCH);
    r.y = __int_as_float(hi * PITCH);
    r.z = a;
    r.w = 0.0f;
    g_scratch[idx] = r;
}

// ---- Blackwell packed fp32x2 helpers ----
__device__ __forceinline__ unsigned long long pk2(float v) {
    unsigned long long r;
    asm("mov.b64 %0, {%1, %2};" : "=l"(r) : "f"(v), "f"(v));
    return r;
}
__device__ __forceinline__ unsigned long long ffma2(unsigned long long a,
                                                    unsigned long long b,
                                                    unsigned long long c) {
    unsigned long long d;
    asm("fma.rn.f32x2 %0, %1, %2, %3;" : "=l"(d) : "l"(a), "l"(b), "l"(c));
    return d;
}

// ---- mbarrier / TMA helpers ----
__device__ __forceinline__ void mbar_init(uint32_t addr, uint32_t count) {
    asm volatile("mbarrier.init.shared.b64 [%0], %1;" :: "r"(addr), "r"(count) : "memory");
}
__device__ __forceinline__ void mbar_expect_tx(uint32_t addr, uint32_t bytes) {
    asm volatile("mbarrier.arrive.expect_tx.shared.b64 _, [%0], %1;"
                 :: "r"(addr), "r"(bytes) : "memory");
}
__device__ __forceinline__ void mbar_arrive(uint32_t addr) {
    asm volatile("mbarrier.arrive.release.cta.shared::cta.b64 _, [%0];"
                 :: "r"(addr) : "memory");
}
__device__ __forceinline__ void mbar_wait_acq(uint32_t addr, uint32_t parity) {
    asm volatile(
        "{\n\t.reg .pred P;\n"
        "WL_%=:\n\t"
        "mbarrier.try_wait.parity.acquire.cta.shared::cta.b64 P, [%0], %1, 0x989680;\n\t"
        "@!P bra WL_%=;\n\t}"
        :: "r"(addr), "r"(parity) : "memory");
}
__device__ __forceinline__ void tma_load_2d(uint32_t smem_dst, const CUtensorMap* tmap,
                                            int cx, int cy, uint32_t mbar) {
    asm volatile(
        "cp.async.bulk.tensor.2d.shared::cta.global.tile.mbarrier::complete_tx::bytes "
        "[%0], [%1, {%2, %3}], [%4];"
        :: "r"(smem_dst), "l"(tmap), "r"(cx), "r"(cy), "r"(mbar) : "memory");
}
__device__ __forceinline__ void bulk_copy_g2s(uint32_t smem_dst, const void* gsrc,
                                              uint32_t bytes, uint32_t mbar) {
    unsigned long long ga = (unsigned long long)__cvta_generic_to_global(gsrc);
    asm volatile(
        "cp.async.bulk.shared::cta.global.mbarrier::complete_tx::bytes [%0], [%1], %2, [%3];"
        :: "r"(smem_dst), "l"(ga), "r"(bytes), "r"(mbar) : "memory");
}

__global__ void __launch_bounds__(NTHR, 2) encode_kernel(
        const __grid_constant__ CUtensorMap tmap,
        float* __restrict__ out) {
    __shared__ float  tile[NBUF][TILE_FLOATS];
    __shared__ float4 sscr[NBUF][B_DIM];
    __shared__ __align__(8) unsigned long long mb_full[NBUF];
    __shared__ __align__(8) unsigned long long mb_empty[NBUF];

    const int tid  = threadIdx.x;
    const int lane = tid & 31;
    const int hg   = tid & 7;        // which float4 within the 32-column slice
    const int bg   = tid >> 3;       // batch group: 4 batches per thread (0..63)
    const int h0   = blockIdx.x * HC;
    const int h    = h0 + hg * 4;
    const bool h_ok = (h < H_DIM);

    if (tid == 0) {
#pragma unroll
        for (int i = 0; i < NBUF; ++i) {
            mbar_init((uint32_t)__cvta_generic_to_shared(&mb_full[i]), 1);
            mbar_init((uint32_t)__cvta_generic_to_shared(&mb_empty[i]), NWARP);
        }
        asm volatile("fence.proxy.async.shared::cta;" ::: "memory");
    }
    __syncthreads();          // the only block-wide barrier

    // producer: issue stage d into slot d%NBUF (caller guarantees slot free)
    auto issue = [&](int d) {
        int slot = d % NBUF;
        uint32_t bar = (uint32_t)__cvta_generic_to_shared(&mb_full[slot]);
        mbar_expect_tx(bar, TILE_BYTES + SCR_BYTES);
        tma_load_2d((uint32_t)__cvta_generic_to_shared(&tile[slot][0]),
                    &tmap, h0, d * L_DIM, bar);
        bulk_copy_g2s((uint32_t)__cvta_generic_to_shared(&sscr[slot][0]),
                      &g_scratch[d * B_DIM], SCR_BYTES, bar);
    };

    if (tid == 0) {
#pragma unroll
        for (int d = 0; d < NBUF - 1; ++d) issue(d);   // prologue fill
    }

    unsigned long long acc[4][2];
#pragma unroll
    for (int i = 0; i < 4; ++i) { acc[i][0] = 0ull; acc[i][1] = 0ull; }

    for (int d = 0; d < D_DIM; ++d) {
        const int slot = d % NBUF;
        mbar_wait_acq((uint32_t)__cvta_generic_to_shared(&mb_full[slot]),
                      (uint32_t)((d / NBUF) & 1));

        const float*  tb = tile[slot];
        const float4* sc = &sscr[slot][bg * 4];
#pragma unroll
        for (int i = 0; i < 4; ++i) {
            float4 s = sc[i];               // LDS.128 broadcast within 8-lane group
            int off_lo = __float_as_int(s.x);
            int off_hi = __float_as_int(s.y);
            float a  = s.z;
            unsigned long long wa = pk2(a);
            unsigned long long w0 = pk2(1.0f - a);
            ulonglong2 vl = *reinterpret_cast<const ulonglong2*>(tb + off_lo + hg * 4);
            ulonglong2 vh = *reinterpret_cast<const ulonglong2*>(tb + off_hi + hg * 4);
            acc[i][0] = ffma2(w0, vl.x, acc[i][0]);
            acc[i][1] = ffma2(w0, vl.y, acc[i][1]);
            acc[i][0] = ffma2(wa, vh.x, acc[i][0]);
            acc[i][1] = ffma2(wa, vh.y, acc[i][1]);
        }

        __syncwarp();
        if (lane == 0)
            mbar_arrive((uint32_t)__cvta_generic_to_shared(&mb_empty[slot]));

        // producer refills: stage d+NBUF-1 goes into slot (d-1+NBUF)%NBUF,
        // which is free once all warps consumed stage d-1
        if (tid == 0) {
            int dn = d + NBUF - 1;
            if (dn < D_DIM) {
                int j = dn / NBUF;          // reuse index of that slot
                if (j >= 1)
                    mbar_wait_acq((uint32_t)__cvta_generic_to_shared(&mb_empty[dn % NBUF]),
                                  (uint32_t)((j - 1) & 1));
                issue(dn);
            }
        }
    }

    if (h_ok) {
#pragma unroll
        for (int i = 0; i < 4; ++i) {
            ulonglong2 o;
            o.x = acc[i][0];
            o.y = acc[i][1];
            *reinterpret_cast<ulonglong2*>(out + (size_t)(bg * 4 + i) * H_DIM + h) = o;
        }
    }
}

__global__ void __launch_bounds__(256) normalize_kernel(float* __restrict__ out) {
    int b = blockIdx.x;
    float* row = out + (size_t)b * H_DIM;

    float ss = 0.0f;
    for (int i = threadIdx.x * 4; i < H_DIM; i += 256 * 4) {
        float4 v = *reinterpret_cast<const float4*>(row + i);
        ss += v.x * v.x + v.y * v.y + v.z * v.z + v.w * v.w;
    }
#pragma unroll
    for (int o = 16; o; o >>= 1) ss += __shfl_down_sync(0xffffffffu, ss, o);

    __shared__ float red[8];
    __shared__ float inv_s;
    if ((threadIdx.x & 31) == 0) red[threadIdx.x >> 5] = ss;
    __syncthreads();
    if (threadIdx.x == 0) {
        float t = 0.0f;
#pragma unroll
        for (int i = 0; i < 8; ++i) t += red[i];
        inv_s = rsqrtf(t);
    }
    __syncthreads();
    float inv = inv_s;

    for (int i = threadIdx.x * 4; i < H_DIM; i += 256 * 4) {
        float4 v = *reinterpret_cast<const float4*>(row + i);
        v.x *= inv; v.y *= inv; v.z *= inv; v.w *= inv;
        *reinterpret_cast<float4*>(row + i) = v;
    }
}

// ---- host-side tensor-map construction (no -lcuda needed) ----
typedef CUresult (*encode_tiled_fn)(
    CUtensorMap*, CUtensorMapDataType, cuuint32_t, void*,
    const cuuint64_t*, const cuuint64_t*, const cuuint32_t*, const cuuint32_t*,
    CUtensorMapInterleave, CUtensorMapSwizzle, CUtensorMapL2promotion,
    CUtensorMapFloatOOBfill);

static encode_tiled_fn get_encode_fn() {
    static encode_tiled_fn fn = nullptr;
    if (!fn) {
        void* p = nullptr;
        cudaDriverEntryPointQueryResult qr;
        cudaGetDriverEntryPointByVersion("cuTensorMapEncodeTiled", &p, 12000,
                                         cudaEnableDefault, &qr);
        fn = (encode_tiled_fn)p;
    }
    return fn;
}

extern "C" void kernel_launch(void* const* d_in, const int* in_sizes, int n_in,
                              void* d_out, int out_size) {
    const float* x;
    const float* base;
    if (in_sizes[0] == B_DIM * D_DIM) {
        x = (const float*)d_in[0];
        base = (const float*)d_in[1];
    } else {
        x = (const float*)d_in[1];
        base = (const float*)d_in[0];
    }
    float* out = (float*)d_out;

    // base viewed as 2D: [D*L rows of H floats]; box = [HC, L]
    // L2 promotion 256B: each block's 128B TMA row-read also fills the
    // neighbor block's island into L2 -> DRAM sees 256B-granular reads.
    CUtensorMap tmap;
    memset(&tmap, 0, sizeof(tmap));
    {
        encode_tiled_fn enc = get_encode_fn();
        cuuint64_t dims[2]    = {(cuuint64_t)H_DIM, (cuuint64_t)(D_DIM * L_DIM)};
        cuuint64_t strides[1] = {(cuuint64_t)H_DIM * 4};
        cuuint32_t box[2]     = {HC, L_DIM};
        cuuint32_t estr[2]    = {1, 1};
        enc(&tmap, CU_TENSOR_MAP_DATA_TYPE_FLOAT32, 2, (void*)base,
            dims, strides, box, estr,
            CU_TENSOR_MAP_INTERLEAVE_NONE, CU_TENSOR_MAP_SWIZZLE_NONE,
            CU_TENSOR_MAP_L2_PROMOTION_L2_256B, CU_TENSOR_MAP_FLOAT_OOB_FILL_NONE);
    }

    // two dummy launches keep the ncu -s 5 -c 1 window on encode
    dummy_kernel<<<1, 32>>>();
    dummy_kernel<<<1, 32>>>();

    precomp_kernel<<<(D_DIM * B_DIM + 255) / 256, 256>>>(x);

    int nblocks = (H_DIM + HC - 1) / HC;   // 313
    encode_kernel<<<nblocks, NTHR>>>(tmap, out);

    normalize_kernel<<<B_DIM, 256>>>(out);
}

// round 9
// speedup vs baseline: 1.6490x; 1.1569x over previous
#include <cuda_runtime.h>
#include <cuda.h>
#include <cstdint>
#include <cstddef>
#include <cstring>

#define D_DIM 64
#define L_DIM 100
#define B_DIM 256
#define H_DIM 10000
#define HC    32                 // h-columns per block
#define PITCH 32                 // floats per tile row (dense, TMA-packed)
#define DPB   16                 // d's per block (D split 4 ways)
#define NPART 4
#define TILE_FLOATS (L_DIM * PITCH)
#define TILE_BYTES  (TILE_FLOATS * 4)       // 12800
#define SCR_BYTES   (B_DIM * 8)             // 2048
#define NBUF  6
#define NTHR  512
#define NWARP (NTHR / 32)

// per-(d,b): {off_lo | off_hi<<16, alpha bits}
__device__ uint2 g_scr2[D_DIM * B_DIM];
// partial sums for D-parts 1..3 (part 0 writes d_out directly)
__device__ float g_part[NPART - 1][B_DIM * H_DIM];
__device__ int   g_dummy;

__global__ void dummy_kernel() {
    if (threadIdx.x == 0 && blockIdx.x == 0) g_dummy = 1;
}

__global__ void __launch_bounds__(256) precomp_kernel(const float* __restrict__ x) {
    int idx = blockIdx.x * 256 + threadIdx.x;
    if (idx >= D_DIM * B_DIM) return;
    int d = idx >> 8;
    int b = idx & 255;
    float xv = x[b * D_DIM + d];
    float xn = fminf(fmaxf(xv * (float)(L_DIM - 1), 0.0f), (float)(L_DIM - 1));
    float fl = floorf(xn);
    int lo = (int)fl;
    int hi = min(lo + 1, L_DIM - 1);
    float a = xn - fl;
    uint2 r;
    r.x = (uint32_t)(lo * PITCH) | ((uint32_t)(hi * PITCH) << 16);
    r.y = __float_as_uint(a);
    g_scr2[idx] = r;
}

// ---- Blackwell packed fp32x2 helpers ----
__device__ __forceinline__ unsigned long long pk2(float v) {
    unsigned long long r;
    asm("mov.b64 %0, {%1, %2};" : "=l"(r) : "f"(v), "f"(v));
    return r;
}
__device__ __forceinline__ unsigned long long ffma2(unsigned long long a,
                                                    unsigned long long b,
                                                    unsigned long long c) {
    unsigned long long d;
    asm("fma.rn.f32x2 %0, %1, %2, %3;" : "=l"(d) : "l"(a), "l"(b), "l"(c));
    return d;
}

// ---- mbarrier / TMA helpers ----
__device__ __forceinline__ void mbar_init(uint32_t addr, uint32_t count) {
    asm volatile("mbarrier.init.shared.b64 [%0], %1;" :: "r"(addr), "r"(count) : "memory");
}
__device__ __forceinline__ void mbar_expect_tx(uint32_t addr, uint32_t bytes) {
    asm volatile("mbarrier.arrive.expect_tx.shared.b64 _, [%0], %1;"
                 :: "r"(addr), "r"(bytes) : "memory");
}
__device__ __forceinline__ void mbar_arrive(uint32_t addr) {
    asm volatile("mbarrier.arrive.release.cta.shared::cta.b64 _, [%0];"
                 :: "r"(addr) : "memory");
}
__device__ __forceinline__ void mbar_wait_acq(uint32_t addr, uint32_t parity) {
    asm volatile(
        "{\n\t.reg .pred P;\n"
        "WL_%=:\n\t"
        "mbarrier.try_wait.parity.acquire.cta.shared::cta.b64 P, [%0], %1, 0x989680;\n\t"
        "@!P bra WL_%=;\n\t}"
        :: "r"(addr), "r"(parity) : "memory");
}
__device__ __forceinline__ void tma_load_2d(uint32_t smem_dst, const CUtensorMap* tmap,
                                            int cx, int cy, uint32_t mbar) {
    asm volatile(
        "cp.async.bulk.tensor.2d.shared::cta.global.tile.mbarrier::complete_tx::bytes "
        "[%0], [%1, {%2, %3}], [%4];"
        :: "r"(smem_dst), "l"(tmap), "r"(cx), "r"(cy), "r"(mbar) : "memory");
}
__device__ __forceinline__ void bulk_copy_g2s(uint32_t smem_dst, const void* gsrc,
                                              uint32_t bytes, uint32_t mbar) {
    unsigned long long ga = (unsigned long long)__cvta_generic_to_global(gsrc);
    asm volatile(
        "cp.async.bulk.shared::cta.global.mbarrier::complete_tx::bytes [%0], [%1], %2, [%3];"
        :: "r"(smem_dst), "l"(ga), "r"(bytes), "r"(mbar) : "memory");
}

__global__ void __launch_bounds__(NTHR, 2) encode_kernel(
        const __grid_constant__ CUtensorMap tmap,
        float* __restrict__ out) {
    __shared__ float tile[NBUF][TILE_FLOATS];
    __shared__ uint2 sscr[NBUF][B_DIM];
    __shared__ __align__(8) unsigned long long mb_full[NBUF];
    __shared__ __align__(8) unsigned long long mb_empty[NBUF];

    const int tid   = threadIdx.x;
    const int lane  = tid & 31;
    const int hg    = tid & 7;        // which float4 within the 32-column slice
    const int bg    = tid >> 3;       // batch group: 4 batches per thread (0..63)
    const int slice = blockIdx.x >> 2;
    const int part  = blockIdx.x & 3;
    const int d0    = part * DPB;
    const int h0    = slice * HC;
    const int h     = h0 + hg * 4;
    const bool h_ok = (h < H_DIM);

    float* dst = (part == 0) ? out : &g_part[part - 1][0];

    if (tid == 0) {
#pragma unroll
        for (int i = 0; i < NBUF; ++i) {
            mbar_init((uint32_t)__cvta_generic_to_shared(&mb_full[i]), 1);
            mbar_init((uint32_t)__cvta_generic_to_shared(&mb_empty[i]), NWARP);
        }
        asm volatile("fence.proxy.async.shared::cta;" ::: "memory");
    }
    __syncthreads();          // the only block-wide barrier

    // producer: issue stage t (d = d0+t) into slot t%NBUF
    auto issue = [&](int t) {
        int slot = t % NBUF;
        int d = d0 + t;
        uint32_t bar = (uint32_t)__cvta_generic_to_shared(&mb_full[slot]);
        mbar_expect_tx(bar, TILE_BYTES + SCR_BYTES);
        tma_load_2d((uint32_t)__cvta_generic_to_shared(&tile[slot][0]),
                    &tmap, h0, d * L_DIM, bar);
        bulk_copy_g2s((uint32_t)__cvta_generic_to_shared(&sscr[slot][0]),
                      &g_scr2[d * B_DIM], SCR_BYTES, bar);
    };

    if (tid == 0) {
#pragma unroll
        for (int t = 0; t < NBUF - 1; ++t) issue(t);   // prologue fill
    }

    unsigned long long acc[4][2];
#pragma unroll
    for (int i = 0; i < 4; ++i) { acc[i][0] = 0ull; acc[i][1] = 0ull; }

    for (int t = 0; t < DPB; ++t) {
        const int slot = t % NBUF;
        mbar_wait_acq((uint32_t)__cvta_generic_to_shared(&mb_full[slot]),
                      (uint32_t)((t / NBUF) & 1));

        const float* tb = tile[slot];
        const uint2* sc = &sscr[slot][bg * 4];
#pragma unroll
        for (int i = 0; i < 4; ++i) {
            uint2 s = sc[i];                // LDS.64 broadcast within 8-lane group
            int off_lo = (int)(s.x & 0xFFFFu);
            int off_hi = (int)(s.x >> 16);
            float a = __uint_as_float(s.y);
            unsigned long long wa = pk2(a);
            unsigned long long w0 = pk2(1.0f - a);
            ulonglong2 vl = *reinterpret_cast<const ulonglong2*>(tb + off_lo + hg * 4);
            ulonglong2 vh = *reinterpret_cast<const ulonglong2*>(tb + off_hi + hg * 4);
            acc[i][0] = ffma2(w0, vl.x, acc[i][0]);
            acc[i][1] = ffma2(w0, vl.y, acc[i][1]);
            acc[i][0] = ffma2(wa, vh.x, acc[i][0]);
            acc[i][1] = ffma2(wa, vh.y, acc[i][1]);
        }

        __syncwarp();
        if (lane == 0)
            mbar_arrive((uint32_t)__cvta_generic_to_shared(&mb_empty[slot]));

        if (tid == 0) {
            int tn = t + NBUF - 1;
            if (tn < DPB) {
                int j = tn / NBUF;          // reuse index of that slot
                if (j >= 1)
                    mbar_wait_acq((uint32_t)__cvta_generic_to_shared(&mb_empty[tn % NBUF]),
                                  (uint32_t)((j - 1) & 1));
                issue(tn);
            }
        }
    }

    if (h_ok) {
#pragma unroll
        for (int i = 0; i < 4; ++i) {
            ulonglong2 o;
            o.x = acc[i][0];
            o.y = acc[i][1];
            *reinterpret_cast<ulonglong2*>(dst + (size_t)(bg * 4 + i) * H_DIM + h) = o;
        }
    }
}

__global__ void __launch_bounds__(256) normalize_kernel(float* __restrict__ out) {
    int b = blockIdx.x;
    const size_t off = (size_t)b * H_DIM;
    float* row = out + off;
    const float* p0 = &g_part[0][off];
    const float* p1 = &g_part[1][off];
    const float* p2 = &g_part[2][off];

    float ss = 0.0f;
    for (int i = threadIdx.x * 4; i < H_DIM; i += 256 * 4) {
        float4 v  = *reinterpret_cast<const float4*>(row + i);
        float4 a0 = *reinterpret_cast<const float4*>(p0 + i);
        float4 a1 = *reinterpret_cast<const float4*>(p1 + i);
        float4 a2 = *reinterpret_cast<const float4*>(p2 + i);
        v.x += a0.x + a1.x + a2.x;
        v.y += a0.y + a1.y + a2.y;
        v.z += a0.z + a1.z + a2.z;
        v.w += a0.w + a1.w + a2.w;
        *reinterpret_cast<float4*>(row + i) = v;    // store combined (pre-norm)
        ss += v.x * v.x + v.y * v.y + v.z * v.z + v.w * v.w;
    }
#pragma unroll
    for (int o = 16; o; o >>= 1) ss += __shfl_down_sync(0xffffffffu, ss, o);

    __shared__ float red[8];
    __shared__ float inv_s;
    if ((threadIdx.x & 31) == 0) red[threadIdx.x >> 5] = ss;
    __syncthreads();
    if (threadIdx.x == 0) {
        float t = 0.0f;
#pragma unroll
        for (int i = 0; i < 8; ++i) t += red[i];
        inv_s = rsqrtf(t);
    }
    __syncthreads();
    float inv = inv_s;

    for (int i = threadIdx.x * 4; i < H_DIM; i += 256 * 4) {
        float4 v = *reinterpret_cast<const float4*>(row + i);
        v.x *= inv; v.y *= inv; v.z *= inv; v.w *= inv;
        *reinterpret_cast<float4*>(row + i) = v;
    }
}

// ---- host-side tensor-map construction (no -lcuda needed) ----
typedef CUresult (*encode_tiled_fn)(
    CUtensorMap*, CUtensorMapDataType, cuuint32_t, void*,
    const cuuint64_t*, const cuuint64_t*, const cuuint32_t*, const cuuint32_t*,
    CUtensorMapInterleave, CUtensorMapSwizzle, CUtensorMapL2promotion,
    CUtensorMapFloatOOBfill);

static encode_tiled_fn get_encode_fn() {
    static encode_tiled_fn fn = nullptr;
    if (!fn) {
        void* p = nullptr;
        cudaDriverEntryPointQueryResult qr;
        cudaGetDriverEntryPointByVersion("cuTensorMapEncodeTiled", &p, 12000,
                                         cudaEnableDefault, &qr);
        fn = (encode_tiled_fn)p;
    }
    return fn;
}

extern "C" void kernel_launch(void* const* d_in, const int* in_sizes, int n_in,
                              void* d_out, int out_size) {
    const float* x;
    const float* base;
    if (in_sizes[0] == B_DIM * D_DIM) {
        x = (const float*)d_in[0];
        base = (const float*)d_in[1];
    } else {
        x = (const float*)d_in[1];
        base = (const float*)d_in[0];
    }
    float* out = (float*)d_out;

    // base viewed as 2D: [D*L rows of H floats]; box = [HC, L]
    CUtensorMap tmap;
    memset(&tmap, 0, sizeof(tmap));
    {
        encode_tiled_fn enc = get_encode_fn();
        cuuint64_t dims[2]    = {(cuuint64_t)H_DIM, (cuuint64_t)(D_DIM * L_DIM)};
        cuuint64_t strides[1] = {(cuuint64_t)H_DIM * 4};
        cuuint32_t box[2]     = {HC, L_DIM};
        cuuint32_t estr[2]    = {1, 1};
        enc(&tmap, CU_TENSOR_MAP_DATA_TYPE_FLOAT32, 2, (void*)base,
            dims, strides, box, estr,
            CU_TENSOR_MAP_INTERLEAVE_NONE, CU_TENSOR_MAP_SWIZZLE_NONE,
            CU_TENSOR_MAP_L2_PROMOTION_L2_128B, CU_TENSOR_MAP_FLOAT_OOB_FILL_NONE);
    }

    // two dummy launches keep the ncu -s 5 -c 1 window on encode
    dummy_kernel<<<1, 32>>>();
    dummy_kernel<<<1, 32>>>();

    precomp_kernel<<<(D_DIM * B_DIM + 255) / 256, 256>>>(x);

    int nslices = (H_DIM + HC - 1) / HC;   // 313
    encode_kernel<<<nslices * NPART, NTHR>>>(tmap, out);

    normalize_kernel<<<B_DIM, 256>>>(out);
}